// round 15
// baseline (speedup 1.0000x reference)
#include <cuda_runtime.h>
#include <cuda_fp16.h>
#include <math.h>
#include <stdint.h>

#define N_TOK 4096
#define DIM   1024
#define HID   768
#define NE    23
#define TOPK  3
#define NSLOT (N_TOK * TOPK)

#define TBM 128
#define TBN 128
#define TBK 64
#define A_STRIDE 144     // 128B data + 16B pad
#define B_STRIDE 272     // 256B data + 16B pad
#define A_STG   18432    // 128 * 144
#define NSTAGE_A 4
#define B_OFF   (NSTAGE_A * A_STG)          // 73728
#define B_STG   17408                       // 64 * 272
#define SMEM_SZ (B_OFF + 2 * B_STG)         // 108544 (epilogue 67584 fits inside)

#define AUX_NB  64
#define AUX_TPB (N_TOK / AUX_NB)

#define GATE_TPB 8
#define GATE_SMEM ((DIM * NE + GATE_TPB * DIM) * 4)

// ---------------- scratch ----------------
__device__ float g_gw[(size_t)N_TOK * NE];
__device__ int   g_counts[NE];
__device__ int   g_list[(size_t)NE * N_TOK];
__device__ float g_tw[NSLOT];
__device__ float g_partial[AUX_NB * NE];
__device__ __half g_Yrh[(size_t)NSLOT * DIM];

__device__ __half g_xh[(size_t)N_TOK * DIM];
__device__ __half g_Hsh[(size_t)N_TOK * HID];
__device__ __half g_Hrh[(size_t)NSLOT * HID];

__device__ __forceinline__ float gelu_exact(float v) {
    return 0.5f * v * (1.0f + erff(v * 0.7071067811865476f));
}
__device__ __forceinline__ uint32_t smem_u32(const void* p) {
    uint32_t a;
    asm("{ .reg .u64 t; cvta.to.shared.u64 t, %1; cvt.u32.u64 %0, t; }" : "=r"(a) : "l"(p));
    return a;
}
__device__ __forceinline__ void ldsm_x4(uint32_t addr, uint32_t* r) {
    asm volatile("ldmatrix.sync.aligned.m8n8.x4.shared.b16 {%0,%1,%2,%3}, [%4];"
                 : "=r"(r[0]), "=r"(r[1]), "=r"(r[2]), "=r"(r[3]) : "r"(addr));
}
__device__ __forceinline__ void ldsm_x4_t(uint32_t addr, uint32_t* r) {
    asm volatile("ldmatrix.sync.aligned.m8n8.x4.trans.shared.b16 {%0,%1,%2,%3}, [%4];"
                 : "=r"(r[0]), "=r"(r[1]), "=r"(r[2]), "=r"(r[3]) : "r"(addr));
}
__device__ __forceinline__ void mma_f16(float* c, const uint32_t* a, uint32_t b0, uint32_t b1) {
    asm volatile("mma.sync.aligned.m16n8k16.row.col.f32.f16.f16.f32 "
                 "{%0,%1,%2,%3}, {%4,%5,%6,%7}, {%8,%9}, {%0,%1,%2,%3};"
                 : "+f"(c[0]), "+f"(c[1]), "+f"(c[2]), "+f"(c[3])
                 : "r"(a[0]), "r"(a[1]), "r"(a[2]), "r"(a[3]), "r"(b0), "r"(b1));
}
__device__ __forceinline__ void cpa16(uint32_t dst, const void* src) {
    asm volatile("cp.async.cg.shared.global [%0], [%1], 16;" :: "r"(dst), "l"(src));
}
__device__ __forceinline__ void cpa_commit() {
    asm volatile("cp.async.commit_group;");
}
template<int N> __device__ __forceinline__ void cpa_wait() {
    asm volatile("cp.async.wait_group %0;" :: "n"(N));
}
__device__ __forceinline__ uint32_t pack2h(__half a, __half b) {
    return (uint32_t)__half_as_ushort(a) | ((uint32_t)__half_as_ushort(b) << 16);
}
__device__ __forceinline__ uint32_t cvt2h(float a, float b) {
    return pack2h(__float2half_rn(a), __float2half_rn(b));
}

// ---------------- prep: x -> fp16 (+ zero expert counters) ----------------
__global__ void cvt16_kernel(const float4* __restrict__ src, uint4* __restrict__ dst, int n16)
{
    if (blockIdx.x == 0 && threadIdx.x < NE) g_counts[threadIdx.x] = 0;
    int i = blockIdx.x * 256 + threadIdx.x;
    if (i < n16) {
        float4 a = src[4 * i];
        float4 b = src[4 * i + 1];
        float4 c = src[4 * i + 2];
        float4 d = src[4 * i + 3];
        uint4 o0, o1;
        o0.x = cvt2h(a.x, a.y); o0.y = cvt2h(a.z, a.w);
        o0.z = cvt2h(b.x, b.y); o0.w = cvt2h(b.z, b.w);
        o1.x = cvt2h(c.x, c.y); o1.y = cvt2h(c.z, c.w);
        o1.z = cvt2h(d.x, d.y); o1.w = cvt2h(d.z, d.w);
        dst[2 * i]     = o0;
        dst[2 * i + 1] = o1;
    }
}

// ---------------- gate: 8 tokens per block, gW staged in smem ----------------
__global__ void __launch_bounds__(256) gate8_kernel(
    const float* __restrict__ x,
    const float* __restrict__ gW,
    const float* __restrict__ gb,
    const float* __restrict__ rbias)
{
    extern __shared__ float dyn[];
    float* gWs = dyn;
    float* xs  = dyn + DIM * NE;
    __shared__ float gv[GATE_TPB][NE];

    int t = threadIdx.x;
    const float4* gWv = (const float4*)gW;
    for (int i = t; i < DIM * NE / 4; i += 256) ((float4*)gWs)[i] = gWv[i];
    const float4* xv = (const float4*)(x + (size_t)blockIdx.x * GATE_TPB * DIM);
    for (int i = t; i < GATE_TPB * DIM / 4; i += 256) ((float4*)xs)[i] = xv[i];
    __syncthreads();

    int w = t >> 5;
    int l = t & 31;
    int n = blockIdx.x * GATE_TPB + w;

    if (l < NE) {
        const float* xrow = xs + w * DIM;
        float acc = 0.f;
        #pragma unroll 8
        for (int i = 0; i < DIM; i++)
            acc += xrow[i] * gWs[i * NE + l];
        gv[w][l] = 1.0f / (1.0f + expf(-(acc + gb[l])));
    }
    __syncwarp();

    float gsum = 0.f;
    #pragma unroll
    for (int q = 0; q < NE; q++) gsum += gv[w][q];
    if (l < NE) g_gw[(size_t)n * NE + l] = gv[w][l] / gsum;

    if (l == 0) {
        int   idx[TOPK];
        float wv[TOPK];
        unsigned used = 0;
        for (int k = 0; k < TOPK; k++) {
            float best = -1e30f; int bi = 0;
            for (int q = 0; q < NE; q++) {
                if (used & (1u << q)) continue;
                float s = gv[w][q] + rbias[q];
                if (s > best) { best = s; bi = q; }
            }
            used |= (1u << bi);
            idx[k] = bi;
            wv[k]  = gv[w][bi];
        }
        float ws = wv[0] + wv[1] + wv[2];
        for (int k = 0; k < TOPK; k++) {
            int slot = n * TOPK + k;
            g_tw[slot] = wv[k] / ws;
            int pos = atomicAdd(&g_counts[idx[k]], 1);
            g_list[(size_t)idx[k] * N_TOK + pos] = slot;
        }
    }
}

// ---------------- aux phase 1 ----------------
__global__ void aux1_kernel()
{
    __shared__ float sm[AUX_TPB * NE];
    int b = blockIdx.x;
    int t = threadIdx.x;
    const float* src = g_gw + (size_t)b * AUX_TPB * NE;
    for (int i = t; i < AUX_TPB * NE; i += 256) sm[i] = src[i];
    __syncthreads();
    if (t < NE) {
        float s = 0.f;
        #pragma unroll
        for (int r = 0; r < AUX_TPB; r++) s += sm[r * NE + t];
        g_partial[b * NE + t] = s;
    }
}

// ---------------- fp16 GEMM, TBK=64, B in two waves ----------------
template<int KDIM, int NOUT, bool MLP1P>
__global__ void __launch_bounds__(256, 2) mma_mlp(
    const __half* __restrict__ ArH, const __half* __restrict__ AsH,
    const float* __restrict__ BrF, const float* __restrict__ BsF,
    const float* __restrict__ biasR, const float* __restrict__ biasS,
    float* __restrict__ OutSF,
    __half* __restrict__ OutRH, __half* __restrict__ OutSH)
{
    constexpr int NC = KDIM / TBK;

    int ez = blockIdx.z;
    bool sh = (ez == NE);
    int cnt = sh ? N_TOK : g_counts[ez];
    int m0  = blockIdx.x * TBM;
    if (m0 >= cnt) return;
    int n0  = blockIdx.y * TBN;

    extern __shared__ char smem[];
    uint32_t sbase = smem_u32(smem);

    int tid  = threadIdx.x;
    int wid  = tid >> 5;
    int lane = tid & 31;
    int wm   = wid >> 2;
    int wn   = wid & 3;

    const __half* AH  = sh ? AsH : ArH;
    const float*  BF  = sh ? BsF : (BrF + (size_t)ez * KDIM * NOUT);
    const float* bias = sh ? biasS : (biasR + (size_t)ez * NOUT);

    // A: thread t -> row t>>1, half t&1 (32 elems = 4x16B units)
    int arow = tid >> 1;
    int au   = tid & 1;
    int gi_a = m0 + arow;
    int grow;
    if (sh) {
        grow = gi_a;
    } else {
        int gg   = (gi_a < cnt) ? gi_a : (cnt - 1);
        int slot = g_list[(size_t)ez * N_TOK + gg];
        grow = MLP1P ? (slot / TOPK) : slot;
    }
    const __half* ApH = AH + (size_t)grow * KDIM + au * 32;
    uint32_t aoff = (uint32_t)(arow * A_STRIDE + au * 64);

    auto issue_A = [&](int c, int st) {
        uint32_t sA = sbase + (uint32_t)(st * A_STG);
        int k0 = c * TBK;
        cpa16(sA + aoff,      ApH + k0);
        cpa16(sA + aoff + 16, ApH + k0 + 8);
        cpa16(sA + aoff + 32, ApH + k0 + 16);
        cpa16(sA + aoff + 48, ApH + k0 + 24);
        cpa_commit();
    };

    // B: wave w covers k-rows w*32..w*32+31; thread -> row tid>>3, col unit tid&7
    int bk = tid >> 3;
    int bc = tid & 7;
    const float* BpF = BF + (size_t)bk * NOUT + n0 + bc * 8;
    uint32_t boff_base = (uint32_t)(bk * B_STRIDE + bc * 16);

    float4 fb[4];
    auto load_B = [&](int c, int w) {
        size_t k0n = (size_t)(c * TBK + w * 32) * NOUT;
        fb[0] = *(const float4*)(BpF + k0n);
        fb[1] = *(const float4*)(BpF + k0n + 4);
        fb[2] = *(const float4*)(BpF + k0n + 64);
        fb[3] = *(const float4*)(BpF + k0n + 68);
    };
    auto store_B = [&](int bs, int w) {
        char* dst = smem + B_OFF + bs * B_STG + w * (32 * B_STRIDE);
        uint4 v0, v1;
        v0.x = cvt2h(fb[0].x, fb[0].y); v0.y = cvt2h(fb[0].z, fb[0].w);
        v0.z = cvt2h(fb[1].x, fb[1].y); v0.w = cvt2h(fb[1].z, fb[1].w);
        v1.x = cvt2h(fb[2].x, fb[2].y); v1.y = cvt2h(fb[2].z, fb[2].w);
        v1.z = cvt2h(fb[3].x, fb[3].y); v1.w = cvt2h(fb[3].z, fb[3].w);
        *(uint4*)(dst + boff_base)       = v0;
        *(uint4*)(dst + boff_base + 128) = v1;
    };

    // prologue: A 3 ahead; B chunk0 both waves into stage 0, then preload c1 wave0
    issue_A(0, 0);
    if (NC > 1) issue_A(1, 1);
    if (NC > 2) issue_A(2, 2);
    load_B(0, 0); store_B(0, 0);
    load_B(0, 1); store_B(0, 1);
    if (NC > 1) load_B(1, 0);

    float acc[4][4][4];
    #pragma unroll
    for (int i = 0; i < 4; i++)
        #pragma unroll
        for (int j = 0; j < 4; j++)
            #pragma unroll
            for (int q = 0; q < 4; q++) acc[i][j][q] = 0.f;

    uint32_t aAddr = sbase + (uint32_t)((wm * 64 + (lane & 15)) * A_STRIDE + ((lane >> 4) << 4));
    uint32_t bAddr = sbase + B_OFF + (uint32_t)((lane & 15) * B_STRIDE + ((wn * 32 + (lane >> 4) * 8) << 1));

    int st = 0;
    for (int c = 0; c < NC; c++) {
        if (c + 3 <= NC)      cpa_wait<2>();
        else if (c + 2 == NC) cpa_wait<1>();
        else                  cpa_wait<0>();
        __syncthreads();
        if (c + 3 < NC) {
            int st3 = st + 3; if (st3 >= NSTAGE_A) st3 -= NSTAGE_A;
            issue_A(c + 3, st3);
        }
        // B staging for next chunk, split around the first mma half
        if (c + 1 < NC) {
            store_B((c + 1) & 1, 0);   // regs loaded in previous chunk
            load_B(c + 1, 1);
        }
        uint32_t aS = aAddr + (uint32_t)(st * A_STG);
        uint32_t bS = bAddr + (uint32_t)((c & 1) * B_STG);
        // ks = 0,1
        #pragma unroll
        for (int ks = 0; ks < 2; ks++) {
            uint32_t ahF[4][4];
            #pragma unroll
            for (int i = 0; i < 4; i++)
                ldsm_x4(aS + ks * 32 + i * (16 * A_STRIDE), ahF[i]);
            uint32_t bhF[2][4];
            #pragma unroll
            for (int g = 0; g < 2; g++)
                ldsm_x4_t(bS + ks * (16 * B_STRIDE) + g * 32, bhF[g]);
            #pragma unroll
            for (int i = 0; i < 4; i++) {
                #pragma unroll
                for (int j = 0; j < 4; j++) {
                    int g = j >> 1, o = (j & 1) * 2;
                    mma_f16(acc[i][j], ahF[i], bhF[g][o], bhF[g][o + 1]);
                }
            }
        }
        // second half of B staging (wave1 LDG has retired under the mma above)
        if (c + 1 < NC) {
            store_B((c + 1) & 1, 1);
            if (c + 2 < NC) load_B(c + 2, 0);
        }
        // ks = 2,3
        #pragma unroll
        for (int ks = 2; ks < 4; ks++) {
            uint32_t ahF[4][4];
            #pragma unroll
            for (int i = 0; i < 4; i++)
                ldsm_x4(aS + ks * 32 + i * (16 * A_STRIDE), ahF[i]);
            uint32_t bhF[2][4];
            #pragma unroll
            for (int g = 0; g < 2; g++)
                ldsm_x4_t(bS + ks * (16 * B_STRIDE) + g * 32, bhF[g]);
            #pragma unroll
            for (int i = 0; i < 4; i++) {
                #pragma unroll
                for (int j = 0; j < 4; j++) {
                    int g = j >> 1, o = (j & 1) * 2;
                    mma_f16(acc[i][j], ahF[i], bhF[g][o], bhF[g][o + 1]);
                }
            }
        }
        if (++st == NSTAGE_A) st = 0;
    }
    __syncthreads();

    // ---- epilogue: frags -> smem (128 x 132 fp32), then coalesced global ----
    float* epi = (float*)smem;
    {
        int rb = wm * 64 + (lane >> 2);
        int cb = wn * 32 + (lane & 3) * 2;
        #pragma unroll
        for (int i = 0; i < 4; i++) {
            #pragma unroll
            for (int j = 0; j < 4; j++) {
                int r = rb + i * 16;
                int cc = cb + j * 8;
                epi[r * 132 + cc]           = acc[i][j][0];
                epi[r * 132 + cc + 1]       = acc[i][j][1];
                epi[(r + 8) * 132 + cc]     = acc[i][j][2];
                epi[(r + 8) * 132 + cc + 1] = acc[i][j][3];
            }
        }
    }
    __syncthreads();

    for (int i = tid; i < TBM * (TBN / 4); i += 256) {
        int r  = i >> 5;
        int c4 = i & 31;
        int gi = m0 + r;
        if (gi >= cnt) continue;
        float4 v = *(float4*)&epi[r * 132 + c4 * 4];
        int col = n0 + c4 * 4;
        float4 b4 = *(const float4*)(bias + col);
        v.x += b4.x; v.y += b4.y; v.z += b4.z; v.w += b4.w;
        if (MLP1P) {
            v.x = gelu_exact(v.x); v.y = gelu_exact(v.y);
            v.z = gelu_exact(v.z); v.w = gelu_exact(v.w);
            uint2 h;
            h.x = cvt2h(v.x, v.y);
            h.y = cvt2h(v.z, v.w);
            size_t orow;
            __half* OH;
            if (sh) { orow = (size_t)gi; OH = OutSH; }
            else    { orow = (size_t)g_list[(size_t)ez * N_TOK + gi]; OH = OutRH; }
            *(uint2*)(OH + orow * NOUT + col) = h;
        } else {
            if (sh) {
                *(float4*)(OutSF + (size_t)gi * NOUT + col) = v;
            } else {
                int slot = g_list[(size_t)ez * N_TOK + gi];
                float w = g_tw[slot];
                v.x *= w; v.y *= w; v.z *= w; v.w *= w;
                uint2 h;
                h.x = cvt2h(v.x, v.y);
                h.y = cvt2h(v.z, v.w);
                *(uint2*)(OutRH + (size_t)slot * NOUT + col) = h;
            }
        }
    }
}

// ---------------- combine (+ aux scalar in block 0) ----------------
__global__ void combine_kernel(float* __restrict__ out, int out_size)
{
    if (blockIdx.x == 0 && threadIdx.x == 0 && out_size > N_TOK * DIM) {
        float Ps[NE];
        #pragma unroll
        for (int e = 0; e < NE; e++) Ps[e] = 0.f;
        for (int b = 0; b < AUX_NB; b++)
            #pragma unroll
            for (int e = 0; e < NE; e++) Ps[e] += g_partial[b * NE + e];
        float aux = 0.f;
        for (int e = 0; e < NE; e++) {
            float P = Ps[e] / (float)N_TOK;
            float F = ((float)NE * (float)g_counts[e]) / ((float)TOPK * (float)N_TOK);
            aux += P * F;
        }
        out[(size_t)N_TOK * DIM] = aux;
    }
    int idx = blockIdx.x * blockDim.x + threadIdx.x;
    if (idx >= N_TOK * (DIM / 4)) return;
    int n  = idx / (DIM / 4);
    int d4 = idx % (DIM / 4);
    float4 v = ((float4*)out)[idx];
    const uint2* yr = (const uint2*)g_Yrh;
    #pragma unroll
    for (int k = 0; k < TOPK; k++) {
        uint2 y = __ldg(&yr[(size_t)(n * TOPK + k) * (DIM / 4) + d4]);
        __half2 lo = *(__half2*)&y.x;
        __half2 hi = *(__half2*)&y.y;
        v.x += __low2float(lo);  v.y += __high2float(lo);
        v.z += __low2float(hi);  v.w += __high2float(hi);
    }
    ((float4*)out)[idx] = v;
}

// ---------------- launch ----------------
extern "C" void kernel_launch(void* const* d_in, const int* in_sizes, int n_in,
                              void* d_out, int out_size)
{
    const float* x   = (const float*)d_in[0];
    const float* gW  = (const float*)d_in[1];
    const float* gb  = (const float*)d_in[2];
    const float* rb  = (const float*)d_in[3];
    const float* W1  = (const float*)d_in[4];
    const float* b1  = (const float*)d_in[5];
    const float* W2  = (const float*)d_in[6];
    const float* b2  = (const float*)d_in[7];
    const float* sW1 = (const float*)d_in[8];
    const float* sb1 = (const float*)d_in[9];
    const float* sW2 = (const float*)d_in[10];
    const float* sb2 = (const float*)d_in[11];
    float* out = (float*)d_out;

    void* p;
    cudaGetSymbolAddress(&p, g_xh);   __half* xh   = (__half*)p;
    cudaGetSymbolAddress(&p, g_Hsh);  __half* Hsh  = (__half*)p;
    cudaGetSymbolAddress(&p, g_Hrh);  __half* Hrh  = (__half*)p;
    cudaGetSymbolAddress(&p, g_Yrh);  __half* Yrh  = (__half*)p;

    cudaFuncSetAttribute(mma_mlp<DIM, HID, true >, cudaFuncAttributeMaxDynamicSharedMemorySize, SMEM_SZ);
    cudaFuncSetAttribute(mma_mlp<HID, DIM, false>, cudaFuncAttributeMaxDynamicSharedMemorySize, SMEM_SZ);
    cudaFuncSetAttribute(gate8_kernel, cudaFuncAttributeMaxDynamicSharedMemorySize, GATE_SMEM);

    {
        int n16 = N_TOK * DIM / 16;
        cvt16_kernel<<<(n16 + 255) / 256, 256>>>((const float4*)x, (uint4*)xh, n16);  // 0 (+init)
    }
    gate8_kernel<<<N_TOK / GATE_TPB, 256, GATE_SMEM>>>(x, gW, gb, rb);                 // 1

    // 2: MLP1 (merged routed + shared): x -> Hr (slots, gelu, fp16), Hs (tokens)
    mma_mlp<DIM, HID, true ><<<dim3(N_TOK / TBM, HID / TBN, NE + 1), 256, SMEM_SZ>>>(
        xh, xh, W1, sW1, b1, sb1,
        nullptr, Hrh, Hsh);
    // 3: MLP2 (merged): Hr -> Yrh (*tw, fp16), Hs -> out (fp32)
    mma_mlp<HID, DIM, false><<<dim3(N_TOK / TBM, DIM / TBN, NE + 1), 256, SMEM_SZ>>>(
        Hrh, Hsh, W2, sW2, b2, sb2,
        out, Yrh, nullptr);

    aux1_kernel<<<AUX_NB, 256>>>();                                                    // 4
    combine_kernel<<<(N_TOK * (DIM / 4) + 255) / 256, 256>>>(out, out_size);           // 5
}

// round 16
// speedup vs baseline: 1.1376x; 1.1376x over previous
#include <cuda_runtime.h>
#include <cuda_fp16.h>
#include <math.h>
#include <stdint.h>

#define N_TOK 4096
#define DIM   1024
#define HID   768
#define NE    23
#define TOPK  3
#define NSLOT (N_TOK * TOPK)

#define TBM 128
#define TBN 128
#define TBK 32
#define A_STRIDE 80      // 64B data + 16B pad
#define B_STRIDE 272     // 256B data + 16B pad
#define A_STG   10240
#define NSTAGE_A 4
#define B_OFF   (NSTAGE_A * A_STG)          // 40960
#define B_STG   8704                        // 32 * 272
#define EPI_SZ  (128 * 132 * 4)             // 67584
#define SMEM_SZ EPI_SZ

#define GATE_TPB 8
#define GATE_NB  (N_TOK / GATE_TPB)         // 512 blocks
#define GATE_SMEM ((DIM * NE + GATE_TPB * DIM) * 4)

// ---------------- scratch ----------------
__device__ int   g_counts[NE];
__device__ int   g_list[(size_t)NE * N_TOK];
__device__ float g_tw[NSLOT];
__device__ float g_partial[GATE_NB * NE];
__device__ __half g_Yrh[(size_t)NSLOT * DIM];

__device__ __half g_xh[(size_t)N_TOK * DIM];
__device__ __half g_Hsh[(size_t)N_TOK * HID];
__device__ __half g_Hrh[(size_t)NSLOT * HID];

__device__ __forceinline__ float gelu_exact(float v) {
    return 0.5f * v * (1.0f + erff(v * 0.7071067811865476f));
}
__device__ __forceinline__ uint32_t smem_u32(const void* p) {
    uint32_t a;
    asm("{ .reg .u64 t; cvta.to.shared.u64 t, %1; cvt.u32.u64 %0, t; }" : "=r"(a) : "l"(p));
    return a;
}
__device__ __forceinline__ void ldsm_x4(uint32_t addr, uint32_t* r) {
    asm volatile("ldmatrix.sync.aligned.m8n8.x4.shared.b16 {%0,%1,%2,%3}, [%4];"
                 : "=r"(r[0]), "=r"(r[1]), "=r"(r[2]), "=r"(r[3]) : "r"(addr));
}
__device__ __forceinline__ void ldsm_x4_t(uint32_t addr, uint32_t* r) {
    asm volatile("ldmatrix.sync.aligned.m8n8.x4.trans.shared.b16 {%0,%1,%2,%3}, [%4];"
                 : "=r"(r[0]), "=r"(r[1]), "=r"(r[2]), "=r"(r[3]) : "r"(addr));
}
__device__ __forceinline__ void mma_f16(float* c, const uint32_t* a, uint32_t b0, uint32_t b1) {
    asm volatile("mma.sync.aligned.m16n8k16.row.col.f32.f16.f16.f32 "
                 "{%0,%1,%2,%3}, {%4,%5,%6,%7}, {%8,%9}, {%0,%1,%2,%3};"
                 : "+f"(c[0]), "+f"(c[1]), "+f"(c[2]), "+f"(c[3])
                 : "r"(a[0]), "r"(a[1]), "r"(a[2]), "r"(a[3]), "r"(b0), "r"(b1));
}
__device__ __forceinline__ void cpa16(uint32_t dst, const void* src) {
    asm volatile("cp.async.cg.shared.global [%0], [%1], 16;" :: "r"(dst), "l"(src));
}
__device__ __forceinline__ void cpa_commit() {
    asm volatile("cp.async.commit_group;");
}
template<int N> __device__ __forceinline__ void cpa_wait() {
    asm volatile("cp.async.wait_group %0;" :: "n"(N));
}
__device__ __forceinline__ uint32_t pack2h(__half a, __half b) {
    return (uint32_t)__half_as_ushort(a) | ((uint32_t)__half_as_ushort(b) << 16);
}
__device__ __forceinline__ uint32_t cvt2h(float a, float b) {
    return pack2h(__float2half_rn(a), __float2half_rn(b));
}

// ---------------- init: zero expert counters ----------------
__global__ void init_kernel() {
    if (threadIdx.x < NE) g_counts[threadIdx.x] = 0;
}

// ---------------- gate: 8 tokens/block; also emits xh and aux partials ----------------
__global__ void __launch_bounds__(256) gate8_kernel(
    const float* __restrict__ x,
    const float* __restrict__ gW,
    const float* __restrict__ gb,
    const float* __restrict__ rbias)
{
    extern __shared__ float dyn[];
    float* gWs = dyn;                    // DIM*NE
    float* xs  = dyn + DIM * NE;         // GATE_TPB*DIM
    __shared__ float gv[GATE_TPB][NE];
    __shared__ float gvn[GATE_TPB][NE];

    int t = threadIdx.x;
    const float4* gWv = (const float4*)gW;
    for (int i = t; i < DIM * NE / 4; i += 256) ((float4*)gWs)[i] = gWv[i];
    const float4* xv = (const float4*)(x + (size_t)blockIdx.x * GATE_TPB * DIM);
    for (int i = t; i < GATE_TPB * DIM / 4; i += 256) ((float4*)xs)[i] = xv[i];
    __syncthreads();

    // emit fp16 x from staged smem (replaces cvt16 kernel)
    {
        uint2* xhv = (uint2*)(g_xh + (size_t)blockIdx.x * GATE_TPB * DIM);
        for (int i = t; i < GATE_TPB * DIM / 4; i += 256) {
            float4 v = ((float4*)xs)[i];
            xhv[i] = make_uint2(cvt2h(v.x, v.y), cvt2h(v.z, v.w));
        }
    }

    int w = t >> 5;
    int l = t & 31;
    int n = blockIdx.x * GATE_TPB + w;

    if (l < NE) {
        const float* xrow = xs + w * DIM;
        float acc = 0.f;
        #pragma unroll 8
        for (int i = 0; i < DIM; i++)
            acc += xrow[i] * gWs[i * NE + l];
        gv[w][l] = 1.0f / (1.0f + expf(-(acc + gb[l])));
    }
    __syncwarp();

    float gsum = 0.f;
    #pragma unroll
    for (int q = 0; q < NE; q++) gsum += gv[w][q];
    if (l < NE) gvn[w][l] = gv[w][l] / gsum;

    if (l == 0) {
        int   idx[TOPK];
        float wv[TOPK];
        unsigned used = 0;
        for (int k = 0; k < TOPK; k++) {
            float best = -1e30f; int bi = 0;
            for (int q = 0; q < NE; q++) {
                if (used & (1u << q)) continue;
                float s = gv[w][q] + rbias[q];
                if (s > best) { best = s; bi = q; }
            }
            used |= (1u << bi);
            idx[k] = bi;
            wv[k]  = gv[w][bi];
        }
        float ws = wv[0] + wv[1] + wv[2];
        for (int k = 0; k < TOPK; k++) {
            int slot = n * TOPK + k;
            g_tw[slot] = wv[k] / ws;
            int pos = atomicAdd(&g_counts[idx[k]], 1);
            g_list[(size_t)idx[k] * N_TOK + pos] = slot;
        }
    }
    __syncthreads();

    // aux partial: sum of normalized gate weights over this block's 8 tokens
    if (t < NE) {
        float s = 0.f;
        #pragma unroll
        for (int r = 0; r < GATE_TPB; r++) s += gvn[r][t];
        g_partial[blockIdx.x * NE + t] = s;
    }
}

// ---------------- fp16 GEMM (R14 config): A cp.async 4-stage, B fp32->fp16 in-loader ----------------
template<int KDIM, int NOUT, bool MLP1P>
__global__ void __launch_bounds__(256, 2) mma_mlp(
    const __half* __restrict__ ArH, const __half* __restrict__ AsH,
    const float* __restrict__ BrF, const float* __restrict__ BsF,
    const float* __restrict__ biasR, const float* __restrict__ biasS,
    float* __restrict__ OutSF,
    __half* __restrict__ OutRH, __half* __restrict__ OutSH)
{
    constexpr int NC = KDIM / TBK;

    int ez = blockIdx.z;
    bool sh = (ez == NE);
    int cnt = sh ? N_TOK : g_counts[ez];
    int m0  = blockIdx.x * TBM;
    if (m0 >= cnt) return;
    int n0  = blockIdx.y * TBN;

    extern __shared__ char smem[];
    uint32_t sbase = smem_u32(smem);

    int tid  = threadIdx.x;
    int wid  = tid >> 5;
    int lane = tid & 31;
    int wm   = wid >> 2;
    int wn   = wid & 3;

    const __half* AH  = sh ? AsH : ArH;
    const float*  BF  = sh ? BsF : (BrF + (size_t)ez * KDIM * NOUT);
    const float* bias = sh ? biasS : (biasR + (size_t)ez * NOUT);

    int arow = tid >> 1;
    int au   = tid & 1;
    int gi_a = m0 + arow;
    int grow;
    if (sh) {
        grow = gi_a;
    } else {
        int gg   = (gi_a < cnt) ? gi_a : (cnt - 1);
        int slot = g_list[(size_t)ez * N_TOK + gg];
        grow = MLP1P ? (slot / TOPK) : slot;
    }
    const __half* ApH = AH + (size_t)grow * KDIM + au * 16;
    uint32_t aoff = (uint32_t)(arow * A_STRIDE + au * 32);

    auto issue_A = [&](int c, int st) {
        uint32_t sA = sbase + (uint32_t)(st * A_STG);
        int k0 = c * TBK;
        cpa16(sA + aoff,      ApH + k0);
        cpa16(sA + aoff + 16, ApH + k0 + 8);
        cpa_commit();
    };

    int bk = tid >> 3;
    int bc = tid & 7;
    const float* BpF = BF + (size_t)bk * NOUT + n0 + bc * 8;
    uint32_t boff = (uint32_t)(bk * B_STRIDE + bc * 16);

    float4 fb[4];
    auto load_B = [&](int c) {
        size_t k0n = (size_t)(c * TBK) * NOUT;
        fb[0] = *(const float4*)(BpF + k0n);
        fb[1] = *(const float4*)(BpF + k0n + 4);
        fb[2] = *(const float4*)(BpF + k0n + 64);
        fb[3] = *(const float4*)(BpF + k0n + 68);
    };
    auto store_B = [&](int bs) {
        char* dst = smem + B_OFF + bs * B_STG;
        uint4 v0, v1;
        v0.x = cvt2h(fb[0].x, fb[0].y); v0.y = cvt2h(fb[0].z, fb[0].w);
        v0.z = cvt2h(fb[1].x, fb[1].y); v0.w = cvt2h(fb[1].z, fb[1].w);
        v1.x = cvt2h(fb[2].x, fb[2].y); v1.y = cvt2h(fb[2].z, fb[2].w);
        v1.z = cvt2h(fb[3].x, fb[3].y); v1.w = cvt2h(fb[3].z, fb[3].w);
        *(uint4*)(dst + boff)       = v0;
        *(uint4*)(dst + boff + 128) = v1;
    };

    issue_A(0, 0);
    if (NC > 1) issue_A(1, 1);
    if (NC > 2) issue_A(2, 2);
    load_B(0);
    store_B(0);
    if (NC > 1) load_B(1);

    float acc[4][4][4];
    #pragma unroll
    for (int i = 0; i < 4; i++)
        #pragma unroll
        for (int j = 0; j < 4; j++)
            #pragma unroll
            for (int q = 0; q < 4; q++) acc[i][j][q] = 0.f;

    uint32_t aAddr = sbase + (uint32_t)((wm * 64 + (lane & 15)) * A_STRIDE + ((lane >> 4) << 4));
    uint32_t bAddr = sbase + B_OFF + (uint32_t)((lane & 15) * B_STRIDE + ((wn * 32 + (lane >> 4) * 8) << 1));

    int st = 0;
    for (int c = 0; c < NC; c++) {
        if (c + 3 <= NC)      cpa_wait<2>();
        else if (c + 2 == NC) cpa_wait<1>();
        else                  cpa_wait<0>();
        __syncthreads();
        if (c + 3 < NC) {
            int st3 = st + 3; if (st3 >= NSTAGE_A) st3 -= NSTAGE_A;
            issue_A(c + 3, st3);
        }
        if (c + 1 < NC) {
            store_B((c + 1) & 1);
            if (c + 2 < NC) load_B(c + 2);
        }
        uint32_t aS = aAddr + (uint32_t)(st * A_STG);
        uint32_t bS = bAddr + (uint32_t)((c & 1) * B_STG);
        #pragma unroll
        for (int ks = 0; ks < 2; ks++) {
            uint32_t ahF[4][4];
            #pragma unroll
            for (int i = 0; i < 4; i++)
                ldsm_x4(aS + ks * 32 + i * (16 * A_STRIDE), ahF[i]);
            uint32_t bhF[2][4];
            #pragma unroll
            for (int g = 0; g < 2; g++)
                ldsm_x4_t(bS + ks * (16 * B_STRIDE) + g * 32, bhF[g]);
            #pragma unroll
            for (int i = 0; i < 4; i++) {
                #pragma unroll
                for (int j = 0; j < 4; j++) {
                    int g = j >> 1, o = (j & 1) * 2;
                    mma_f16(acc[i][j], ahF[i], bhF[g][o], bhF[g][o + 1]);
                }
            }
        }
        if (++st == NSTAGE_A) st = 0;
    }
    __syncthreads();

    float* epi = (float*)smem;
    {
        int rb = wm * 64 + (lane >> 2);
        int cb = wn * 32 + (lane & 3) * 2;
        #pragma unroll
        for (int i = 0; i < 4; i++) {
            #pragma unroll
            for (int j = 0; j < 4; j++) {
                int r = rb + i * 16;
                int cc = cb + j * 8;
                epi[r * 132 + cc]           = acc[i][j][0];
                epi[r * 132 + cc + 1]       = acc[i][j][1];
                epi[(r + 8) * 132 + cc]     = acc[i][j][2];
                epi[(r + 8) * 132 + cc + 1] = acc[i][j][3];
            }
        }
    }
    __syncthreads();

    for (int i = tid; i < TBM * (TBN / 4); i += 256) {
        int r  = i >> 5;
        int c4 = i & 31;
        int gi = m0 + r;
        if (gi >= cnt) continue;
        float4 v = *(float4*)&epi[r * 132 + c4 * 4];
        int col = n0 + c4 * 4;
        float4 b4 = *(const float4*)(bias + col);
        v.x += b4.x; v.y += b4.y; v.z += b4.z; v.w += b4.w;
        if (MLP1P) {
            v.x = gelu_exact(v.x); v.y = gelu_exact(v.y);
            v.z = gelu_exact(v.z); v.w = gelu_exact(v.w);
            uint2 h;
            h.x = cvt2h(v.x, v.y);
            h.y = cvt2h(v.z, v.w);
            size_t orow;
            __half* OH;
            if (sh) { orow = (size_t)gi; OH = OutSH; }
            else    { orow = (size_t)g_list[(size_t)ez * N_TOK + gi]; OH = OutRH; }
            *(uint2*)(OH + orow * NOUT + col) = h;
        } else {
            if (sh) {
                *(float4*)(OutSF + (size_t)gi * NOUT + col) = v;
            } else {
                int slot = g_list[(size_t)ez * N_TOK + gi];
                float w = g_tw[slot];
                v.x *= w; v.y *= w; v.z *= w; v.w *= w;
                uint2 h;
                h.x = cvt2h(v.x, v.y);
                h.y = cvt2h(v.z, v.w);
                *(uint2*)(OutRH + (size_t)slot * NOUT + col) = h;
            }
        }
    }
}

// ---------------- combine (+ aux fold in block 0's first warp) ----------------
__global__ void combine_kernel(float* __restrict__ out, int out_size)
{
    __shared__ float Ps[32];
    if (blockIdx.x == 0) {
        int t = threadIdx.x;
        if (t < NE) {
            float s = 0.f;
            for (int b = 0; b < GATE_NB; b++) s += g_partial[b * NE + t];
            Ps[t] = s;
        }
        __syncthreads();
        if (t == 0 && out_size > N_TOK * DIM) {
            float aux = 0.f;
            for (int e = 0; e < NE; e++) {
                float P = Ps[e] / (float)N_TOK;
                float F = ((float)NE * (float)g_counts[e]) / ((float)TOPK * (float)N_TOK);
                aux += P * F;
            }
            out[(size_t)N_TOK * DIM] = aux;
        }
    }
    int idx = blockIdx.x * blockDim.x + threadIdx.x;
    if (idx >= N_TOK * (DIM / 4)) return;
    int n  = idx / (DIM / 4);
    int d4 = idx % (DIM / 4);
    float4 v = ((float4*)out)[idx];
    const uint2* yr = (const uint2*)g_Yrh;
    #pragma unroll
    for (int k = 0; k < TOPK; k++) {
        uint2 y = __ldg(&yr[(size_t)(n * TOPK + k) * (DIM / 4) + d4]);
        __half2 lo = *(__half2*)&y.x;
        __half2 hi = *(__half2*)&y.y;
        v.x += __low2float(lo);  v.y += __high2float(lo);
        v.z += __low2float(hi);  v.w += __high2float(hi);
    }
    ((float4*)out)[idx] = v;
}

// ---------------- launch ----------------
extern "C" void kernel_launch(void* const* d_in, const int* in_sizes, int n_in,
                              void* d_out, int out_size)
{
    const float* x   = (const float*)d_in[0];
    const float* gW  = (const float*)d_in[1];
    const float* gb  = (const float*)d_in[2];
    const float* rb  = (const float*)d_in[3];
    const float* W1  = (const float*)d_in[4];
    const float* b1  = (const float*)d_in[5];
    const float* W2  = (const float*)d_in[6];
    const float* b2  = (const float*)d_in[7];
    const float* sW1 = (const float*)d_in[8];
    const float* sb1 = (const float*)d_in[9];
    const float* sW2 = (const float*)d_in[10];
    const float* sb2 = (const float*)d_in[11];
    float* out = (float*)d_out;

    void* p;
    cudaGetSymbolAddress(&p, g_xh);   __half* xh   = (__half*)p;
    cudaGetSymbolAddress(&p, g_Hsh);  __half* Hsh  = (__half*)p;
    cudaGetSymbolAddress(&p, g_Hrh);  __half* Hrh  = (__half*)p;
    cudaGetSymbolAddress(&p, g_Yrh);  __half* Yrh  = (__half*)p;

    cudaFuncSetAttribute(mma_mlp<DIM, HID, true >, cudaFuncAttributeMaxDynamicSharedMemorySize, SMEM_SZ);
    cudaFuncSetAttribute(mma_mlp<HID, DIM, false>, cudaFuncAttributeMaxDynamicSharedMemorySize, SMEM_SZ);
    cudaFuncSetAttribute(gate8_kernel, cudaFuncAttributeMaxDynamicSharedMemorySize, GATE_SMEM);

    init_kernel<<<1, 32>>>();                                                          // 0
    gate8_kernel<<<GATE_NB, 256, GATE_SMEM>>>(x, gW, gb, rb);                          // 1 (+xh, +aux partials)

    // 2: MLP1 (merged routed + shared): x -> Hr (slots, gelu, fp16), Hs (tokens)
    mma_mlp<DIM, HID, true ><<<dim3(N_TOK / TBM, HID / TBN, NE + 1), 256, SMEM_SZ>>>(
        xh, xh, W1, sW1, b1, sb1,
        nullptr, Hrh, Hsh);
    // 3: MLP2 (merged): Hr -> Yrh (*tw, fp16), Hs -> out (fp32)
    mma_mlp<HID, DIM, false><<<dim3(N_TOK / TBM, DIM / TBN, NE + 1), 256, SMEM_SZ>>>(
        Hrh, Hsh, W2, sW2, b2, sb2,
        out, Yrh, nullptr);

    combine_kernel<<<(N_TOK * (DIM / 4) + 255) / 256, 256>>>(out, out_size);           // 4 (+aux)
}